// round 15
// baseline (speedup 1.0000x reference)
#include <cuda_runtime.h>
#include <cuda_bf16.h>
#include <cuda_fp16.h>
#include <cstdint>

#define BB 4096
#define DD 4096
#define HH 4096
#define OO 1000
#define PP 2048

typedef __half hf;

// ---- device scratch ----
__device__ hf g_Wr1fh[(size_t)HH*DD], g_Wr1fl[(size_t)HH*DD];
__device__ hf g_Wlvfh[(size_t)PP*HH], g_Wlvfl[(size_t)PP*HH];
__device__ hf g_Wg1fh[(size_t)HH*DD], g_Wg1fl[(size_t)HH*DD];
__device__ hf g_Wcfh [(size_t)2*DD*HH], g_Wcfl [(size_t)2*DD*HH]; // Wm/Wl row-interleaved
__device__ hf g_W1fh[(size_t)HH*DD], g_W1fl[(size_t)HH*DD];
__device__ hf g_W2fh[(size_t)OO*HH], g_W2fl[(size_t)OO*HH];
__device__ hf g_pTfh[(size_t)DD*PP], g_pTfl[(size_t)DD*PP];
__device__ hf g_xf  [(size_t)BB*DD];
__device__ hf g_hf  [(size_t)BB*HH];
__device__ hf g_wvf [(size_t)BB*PP];
__device__ hf g_xrf [(size_t)BB*DD];
__device__ hf g_hrf [(size_t)BB*HH];
__device__ hf g_cbf [(size_t)BB*DD];
__device__ hf g_h1f [(size_t)BB*HH];
__device__ float g_bcat[2*DD];
__device__ int g_na, g_perm[BB], g_newpos[BB], g_act[BB], g_posinact[BB], g_mask[BB];

// ---- helpers ----
__device__ __forceinline__ float softplusf(float z) {
    return fmaxf(z, 0.0f) + log1pf(expf(-fabsf(z)));
}
__device__ __forceinline__ uint32_t smem_u32(const void* p) {
    uint32_t a;
    asm("{ .reg .u64 t; cvta.to.shared.u64 t, %1; cvt.u32.u64 %0, t; }" : "=r"(a) : "l"(p));
    return a;
}
__device__ __forceinline__ void cpa16(uint32_t dst, const void* src) {
    asm volatile("cp.async.cg.shared.global [%0], [%1], 16;" :: "r"(dst), "l"(src));
}
__device__ __forceinline__ void ldmx4(uint32_t* r, uint32_t a) {
    asm volatile("ldmatrix.sync.aligned.m8n8.x4.shared.b16 {%0,%1,%2,%3}, [%4];"
                 : "=r"(r[0]), "=r"(r[1]), "=r"(r[2]), "=r"(r[3]) : "r"(a));
}
__device__ __forceinline__ void mma16816h(float* c, const uint32_t* a, const uint32_t* b) {
    asm("mma.sync.aligned.m16n8k16.row.col.f32.f16.f16.f32 "
        "{%0,%1,%2,%3}, {%4,%5,%6,%7}, {%8,%9}, {%0,%1,%2,%3};"
        : "+f"(c[0]), "+f"(c[1]), "+f"(c[2]), "+f"(c[3])
        : "r"(a[0]), "r"(a[1]), "r"(a[2]), "r"(a[3]), "r"(b[0]), "r"(b[1]));
}
__device__ __forceinline__ void split_f16(float v, hf& h, hf& l) {
    h = __float2half_rn(v);
    l = __float2half_rn(v - __half2float(h));
}

// ---- setup ----
__global__ void setup_kernel(const int* __restrict__ mm) {
    __shared__ int wsum[32];
    __shared__ int sTot[2];
    int tid = threadIdx.x, lane = tid & 31, warp = tid >> 5;
    int base = tid * 4;
    int f[4], incl[4], s = 0;
#pragma unroll
    for (int j = 0; j < 4; ++j) { f[j] = (mm[base + j] % 2 != 0); s += f[j]; incl[j] = s; }
    int v = s;
#pragma unroll
    for (int o = 1; o < 32; o <<= 1) { int u = __shfl_up_sync(~0u, v, o); if (lane >= o) v += u; }
    if (lane == 31) wsum[warp] = v;
    __syncthreads();
    if (warp == 0) {
        int w = wsum[lane];
#pragma unroll
        for (int o = 1; o < 32; o <<= 1) { int u = __shfl_up_sync(~0u, w, o); if (lane >= o) w += u; }
        wsum[lane] = w;
        if (lane == 31) sTot[0] = w;
    }
    __syncthreads();
    int Z = BB - sTot[0];
    int thrExcl = (warp ? wsum[warp - 1] : 0) + (v - s);
    int af[4];
#pragma unroll
    for (int j = 0; j < 4; ++j) {
        int i = base + j;
        int ones = thrExcl + incl[j] - f[j];
        int pos = f[j] ? (Z + ones) : (i - ones);
        g_mask[i] = f[j]; g_newpos[i] = pos; g_perm[pos] = i;
        af[j] = (f[j] || pos >= BB / 2);
    }
    __syncthreads();
    int incl2[4], s2 = 0;
#pragma unroll
    for (int j = 0; j < 4; ++j) { s2 += af[j]; incl2[j] = s2; }
    int v2 = s2;
#pragma unroll
    for (int o = 1; o < 32; o <<= 1) { int u = __shfl_up_sync(~0u, v2, o); if (lane >= o) v2 += u; }
    if (lane == 31) wsum[warp] = v2;
    __syncthreads();
    if (warp == 0) {
        int w = wsum[lane];
#pragma unroll
        for (int o = 1; o < 32; o <<= 1) { int u = __shfl_up_sync(~0u, w, o); if (lane >= o) w += u; }
        wsum[lane] = w;
        if (lane == 31) sTot[1] = w;
    }
    __syncthreads();
    int thrExcl2 = (warp ? wsum[warp - 1] : 0) + (v2 - s2);
#pragma unroll
    for (int j = 0; j < 4; ++j) {
        int i = base + j;
        int ab = thrExcl2 + incl2[j] - af[j];
        if (af[j]) { g_act[ab] = i; g_posinact[i] = ab; } else g_posinact[i] = -1;
    }
    if (tid == 0) g_na = sTot[1];
}

// ---- batched weight conversion (all fp16 hi/lo) ----
__global__ void convw_all(const float* __restrict__ Wr1, const float* __restrict__ Wlv,
                          const float* __restrict__ Wg1, const float* __restrict__ Wm,
                          const float* __restrict__ Wl,  const float* __restrict__ W1,
                          const float* __restrict__ W2) {
    int seg = blockIdx.y;
    size_t i = ((size_t)blockIdx.x * 256 + threadIdx.x) * 4;
    const float* src;
    size_t n;
    switch (seg) {
        case 0: src = Wr1; n = (size_t)HH * DD; break;
        case 1: src = Wg1; n = (size_t)HH * DD; break;
        case 2: src = W1;  n = (size_t)HH * DD; break;
        case 3: src = Wlv; n = (size_t)PP * HH; break;
        case 4: src = W2;  n = (size_t)OO * HH; break;
        case 5: src = Wm;  n = (size_t)DD * HH; break;
        default: src = Wl; n = (size_t)DD * HH; break;
    }
    if (i >= n) return;
    float4 v = *reinterpret_cast<const float4*>(src + i);
    float vv[4] = {v.x, v.y, v.z, v.w};
    hf *hi, *lo;
    size_t o = i;
    switch (seg) {
        case 0: hi = g_Wr1fh; lo = g_Wr1fl; break;
        case 1: hi = g_Wg1fh; lo = g_Wg1fl; break;
        case 2: hi = g_W1fh;  lo = g_W1fl;  break;
        case 3: hi = g_Wlvfh; lo = g_Wlvfl; break;
        case 4: hi = g_W2fh;  lo = g_W2fl;  break;
        default: {
            hi = g_Wcfh; lo = g_Wcfl;
            size_t row = i / HH, col = i - row * HH;
            o = (row * 2 + (seg - 5)) * HH + col;
        }
    }
    hf h[4], l[4];
#pragma unroll
    for (int j = 0; j < 4; ++j) split_f16(vv[j], h[j], l[j]);
    reinterpret_cast<__half2*>(hi + o)[0] = __half2(h[0], h[1]);
    reinterpret_cast<__half2*>(hi + o)[1] = __half2(h[2], h[3]);
    reinterpret_cast<__half2*>(lo + o)[0] = __half2(l[0], l[1]);
    reinterpret_cast<__half2*>(lo + o)[1] = __half2(l[2], l[3]);
}

__global__ void convx_kernel(const float* __restrict__ x) {
    int i = blockIdx.y;
    if (i >= g_na) return;
    int r = g_act[i];
    int d = (blockIdx.x * 256 + threadIdx.x) * 4;
    float4 v = *reinterpret_cast<const float4*>(x + (size_t)r * DD + d);
    size_t o = (size_t)i * DD + d;
    reinterpret_cast<__half2*>(g_xf + o)[0] = __floats2half2_rn(v.x, v.y);
    reinterpret_cast<__half2*>(g_xf + o)[1] = __floats2half2_rn(v.z, v.w);
}
__global__ void convpT_kernel(const float* __restrict__ P) {
    __shared__ float tile[32][33];
    int d0 = blockIdx.x * 32, p0 = blockIdx.y * 32;
    int tx = threadIdx.x, ty = threadIdx.y;
#pragma unroll
    for (int i = 0; i < 4; ++i)
        tile[ty + i * 8][tx] = P[(size_t)(p0 + ty + i * 8) * DD + d0 + tx];
    __syncthreads();
#pragma unroll
    for (int i = 0; i < 4; ++i) {
        hf h, l;
        split_f16(tile[tx][ty + i * 8], h, l);
        size_t o = (size_t)(d0 + ty + i * 8) * PP + p0 + tx;
        g_pTfh[o] = h; g_pTfl[o] = l;
    }
}
__global__ void concatb_kernel(const float* __restrict__ a, const float* __restrict__ b) {
    int i = blockIdx.x * 256 + threadIdx.x;   // interleaved: even=bm, odd=bl
    g_bcat[i] = (i & 1) ? b[i >> 1] : a[i >> 1];
}

// ================= fp16 2-product GEMM, 256x128 CTA tile =================
// C[M,N] = A @ (Bh+Bl)^T + bias. 512 threads, 16 warps, warp tile 64x32.
// 3-stage cp.async, 1 CTA/SM, single-buffered fragments.
// flags: 1=Meff g_na, 2=relu, 4=f32 out (Cf), 8=fp16 out (Chf),
//        16=dual-xreg, 32=var/w
#define ROWB 144
#define TILE_A (256 * ROWB)      // 36864
#define TILE_BB (128 * ROWB)     // 18432
#define STAGE_F (TILE_A + 2 * TILE_BB)   // 73728
#define NSTG 3
#define SMEMF (NSTG * STAGE_F + 512)

__global__ void __launch_bounds__(512, 1)
gemm_f16(const hf* __restrict__ A, const hf* __restrict__ Bh, const hf* __restrict__ Bl,
         const float* __restrict__ bias, float* __restrict__ Cf, hf* __restrict__ Chf,
         float* __restrict__ Cw, const float* __restrict__ eps, const hf* __restrict__ Xr,
         int M, int N, int K, int flags)
{
    int Meff = (flags & 1) ? g_na : M;
    int mT = blockIdx.y * 256;
    if (mT >= Meff) return;
    int nT = blockIdx.x * 128;

    extern __shared__ char sm[];
    uint32_t sb = smem_u32(sm);
    float* biasS = reinterpret_cast<float*>(sm + NSTG * STAGE_F);

    int tid = threadIdx.x, wid = tid >> 5, lane = tid & 31;
    int wm = wid & 3, wn = wid >> 2;   // warp tile: 64 rows (wm), 32 cols (wn)

    if (tid < 128) {
        int n = nT + tid;
        biasS[tid] = (bias && n < N) ? bias[n] : 0.0f;
    }

    uint32_t aBase = (wm * 64 + (lane & 15)) * ROWB + ((lane >> 4) & 1) * 16;
    uint32_t bBase = TILE_A + (wn * 32 + ((lane >> 4) & 1) * 8 + (lane & 7)) * ROWB +
                     ((lane >> 3) & 1) * 16;

    float acc[4][4][4];
#pragma unroll
    for (int a = 0; a < 4; ++a)
#pragma unroll
        for (int b = 0; b < 4; ++b)
#pragma unroll
            for (int c = 0; c < 4; ++c) acc[a][b][c] = 0.0f;

    int nK = K / 64;

#define LOAD_STAGE_F(s, k0)                                                      \
    {                                                                            \
        uint32_t st = sb + (s) * STAGE_F;                                        \
        _Pragma("unroll")                                                        \
        for (int i = 0; i < 4; ++i) {                                            \
            int idx = i * 512 + tid;                                             \
            int r = idx >> 3, c16 = idx & 7;                                     \
            int rg = mT + r; rg = rg < Meff ? rg : Meff - 1;                     \
            size_t go = (size_t)rg * K + (k0) + c16 * 8;                         \
            cpa16(st + r * ROWB + c16 * 16, A + go);                             \
        }                                                                        \
        _Pragma("unroll")                                                        \
        for (int i = 0; i < 2; ++i) {                                            \
            int idx = i * 512 + tid;                                             \
            int r = idx >> 3, c16 = idx & 7;                                     \
            int rg = nT + r; rg = rg < N ? rg : N - 1;                           \
            size_t go = (size_t)rg * K + (k0) + c16 * 8;                         \
            uint32_t off = r * ROWB + c16 * 16;                                  \
            cpa16(st + TILE_A + off, Bh + go);                                   \
            cpa16(st + TILE_A + TILE_BB + off, Bl + go);                         \
        }                                                                        \
    }

#define LOAD_FRAGS_F(st, kh, AR, BH, BL)                                         \
    {                                                                            \
        uint32_t ab = (st) + aBase + (kh) * 32;                                  \
        _Pragma("unroll")                                                        \
        for (int ma = 0; ma < 4; ++ma) ldmx4(AR[ma], ab + ma * 16 * ROWB);       \
        uint32_t bb = (st) + bBase + (kh) * 32;                                  \
        _Pragma("unroll")                                                        \
        for (int p = 0; p < 2; ++p) {                                            \
            uint32_t t[4];                                                       \
            ldmx4(t, bb + p * 16 * ROWB);                                        \
            BH[2*p][0] = t[0]; BH[2*p][1] = t[1];                                \
            BH[2*p+1][0] = t[2]; BH[2*p+1][1] = t[3];                            \
            ldmx4(t, bb + p * 16 * ROWB + TILE_BB);                              \
            BL[2*p][0] = t[0]; BL[2*p][1] = t[1];                                \
            BL[2*p+1][0] = t[2]; BL[2*p+1][1] = t[3];                            \
        }                                                                        \
    }

// product-major: 16 independent MMAs between accumulator reuse
#define MMA_BLOCK_F(AR, BH, BL)                                                  \
    {                                                                            \
        _Pragma("unroll")                                                        \
        for (int ma = 0; ma < 4; ++ma)                                           \
            _Pragma("unroll")                                                    \
            for (int na = 0; na < 4; ++na) mma16816h(acc[ma][na], AR[ma], BH[na]);\
        _Pragma("unroll")                                                        \
        for (int ma = 0; ma < 4; ++ma)                                           \
            _Pragma("unroll")                                                    \
            for (int na = 0; na < 4; ++na) mma16816h(acc[ma][na], AR[ma], BL[na]);\
    }

    LOAD_STAGE_F(0, 0);
    asm volatile("cp.async.commit_group;");
    LOAD_STAGE_F(1, 64);
    asm volatile("cp.async.commit_group;");

    uint32_t ar[4][4], brh[4][2], brl[4][2];

    asm volatile("cp.async.wait_group 1;");
    __syncthreads();

    int s_cur = 0;
#pragma unroll 1
    for (int it = 0; it < nK; ++it) {
        uint32_t st = sb + s_cur * STAGE_F;
        LOAD_FRAGS_F(st, 0, ar, brh, brl);
        int ps = it + 2;
        int s_tgt = s_cur + 2 >= NSTG ? s_cur + 2 - NSTG : s_cur + 2;
        if (ps < nK) LOAD_STAGE_F(s_tgt, ps * 64);
        asm volatile("cp.async.commit_group;");
        MMA_BLOCK_F(ar, brh, brl);
        LOAD_FRAGS_F(st, 1, ar, brh, brl);
        MMA_BLOCK_F(ar, brh, brl);
        LOAD_FRAGS_F(st, 2, ar, brh, brl);
        MMA_BLOCK_F(ar, brh, brl);
        LOAD_FRAGS_F(st, 3, ar, brh, brl);
        MMA_BLOCK_F(ar, brh, brl);
        asm volatile("cp.async.wait_group 1;");
        __syncthreads();
        s_cur = s_cur + 1 == NSTG ? 0 : s_cur + 1;
    }

    // ---- epilogue ----
    bool relu = flags & 2, f32s = flags & 4, hfs = flags & 8;
    bool dual = flags & 16, varw = flags & 32;
#pragma unroll
    for (int ma = 0; ma < 4; ++ma) {
#pragma unroll
        for (int rs = 0; rs < 2; ++rs) {
            int m = mT + wm * 64 + ma * 16 + (lane >> 2) + rs * 8;
            if (m >= Meff) continue;
            size_t ro = (size_t)m * N;
            int r = (dual || varw) ? g_act[m] : 0;
#pragma unroll
            for (int na = 0; na < 4; ++na) {
                int nc = wn * 32 + na * 8 + (lane & 3) * 2;
                int n = nT + nc;
                if (n >= N) continue;
                float v0 = acc[ma][na][rs * 2 + 0] + biasS[nc];
                float v1 = acc[ma][na][rs * 2 + 1] + biasS[nc + 1];
                if (relu) { v0 = fmaxf(v0, 0.0f); v1 = fmaxf(v1, 0.0f); }
                if (varw) {
                    float var0 = expf(v0), var1 = expf(v1);
                    float w0 = 1.0f + sqrtf(var0) * eps[(size_t)r * N + n];
                    float w1 = 1.0f + sqrtf(var1) * eps[(size_t)r * N + n + 1];
                    int np = g_newpos[r];
                    if (np >= BB / 2) {
                        size_t jo = (size_t)(np - BB / 2) * N + n;
                        *reinterpret_cast<float2*>(Cf + jo) = make_float2(var0, var1);
                        *reinterpret_cast<float2*>(Cw + jo) = make_float2(w0, w1);
                    }
                    *reinterpret_cast<__half2*>(Chf + ro + n) = __floats2half2_rn(w0, w1);
                } else if (dual) {
                    if (g_mask[r]) {
                        int d = n >> 1;
                        float xr = __half2float(Xr[(size_t)m * DD + d]);
                        float ep = eps[(size_t)r * DD + d];
                        float o = xr * softplusf(v0 + expf(0.5f * v1) * ep);
                        size_t dst = (size_t)g_newpos[r] * DD + d;
                        Chf[dst] = __float2half_rn(o);
                    }
                } else {
                    if (f32s)
                        *reinterpret_cast<float2*>(Cf + ro + n) = make_float2(v0, v1);
                    if (hfs)
                        *reinterpret_cast<__half2*>(Chf + ro + n) = __floats2half2_rn(v0, v1);
                }
            }
        }
    }
}

// ---- elementwise ----
__global__ void copy_kernel(const float* __restrict__ x) {
    int j = blockIdx.y;
    int r = g_perm[j];
    if (g_mask[r]) return;
    int d = (blockIdx.x * 256 + threadIdx.x) * 4;
    float4 v = *reinterpret_cast<const float4*>(x + (size_t)r * DD + d);
    size_t dst = (size_t)j * DD + d;
    reinterpret_cast<__half2*>(g_cbf + dst)[0] = __floats2half2_rn(v.x, v.y);
    reinterpret_cast<__half2*>(g_cbf + dst)[1] = __floats2half2_rn(v.z, v.w);
}

// ---- launch ----
static void* sa(const void* s) { void* p = nullptr; cudaGetSymbolAddress(&p, s); return p; }

extern "C" void kernel_launch(void* const* d_in, const int* in_sizes, int n_in,
                              void* d_out, int out_size) {
    const float* x      = (const float*)d_in[0];
    const int*   mm     = (const int*)d_in[1];
    const float* priors = (const float*)d_in[2];
    const float* W1  = (const float*)d_in[3];
    const float* b1  = (const float*)d_in[4];
    const float* W2  = (const float*)d_in[5];
    const float* b2  = (const float*)d_in[6];
    const float* Wr1 = (const float*)d_in[7];
    const float* br1 = (const float*)d_in[8];
    const float* Wlv = (const float*)d_in[9];
    const float* blv = (const float*)d_in[10];
    const float* Wg1 = (const float*)d_in[11];
    const float* bg1 = (const float*)d_in[12];
    const float* Wm  = (const float*)d_in[13];
    const float* bm  = (const float*)d_in[14];
    const float* Wl  = (const float*)d_in[15];
    const float* bl  = (const float*)d_in[16];
    const float* eps_w = (const float*)d_in[17];
    const float* eps_r = (const float*)d_in[18];
    float* out = (float*)d_out;
    float* out_logits = out;
    float* out_w = out + (size_t)BB * OO;
    float* out_var = out_w + (size_t)(BB - BB / 2) * PP;

    cudaFuncSetAttribute(gemm_f16, cudaFuncAttributeMaxDynamicSharedMemorySize, SMEMF);

    hf *Wr1fh=(hf*)sa(g_Wr1fh), *Wr1fl=(hf*)sa(g_Wr1fl);
    hf *Wlvfh=(hf*)sa(g_Wlvfh), *Wlvfl=(hf*)sa(g_Wlvfl);
    hf *Wg1fh=(hf*)sa(g_Wg1fh), *Wg1fl=(hf*)sa(g_Wg1fl);
    hf *Wcfh=(hf*)sa(g_Wcfh), *Wcfl=(hf*)sa(g_Wcfl);
    hf *W1fh=(hf*)sa(g_W1fh), *W1fl=(hf*)sa(g_W1fl);
    hf *W2fh=(hf*)sa(g_W2fh), *W2fl=(hf*)sa(g_W2fl);
    hf *pTfh=(hf*)sa(g_pTfh), *pTfl=(hf*)sa(g_pTfl);
    hf *xf=(hf*)sa(g_xf), *hff=(hf*)sa(g_hf);
    hf *wvf=(hf*)sa(g_wvf), *xrf=(hf*)sa(g_xrf), *hrf=(hf*)sa(g_hrf);
    hf *cbf=(hf*)sa(g_cbf), *h1f=(hf*)sa(g_h1f);
    float *pbcat=(float*)sa(g_bcat);

    dim3 blk(512);
    const int MT = BB / 256;   // 16 m-tiles

    setup_kernel<<<1, 1024>>>(mm);                                  // 0
    convx_kernel<<<dim3(DD/1024, BB), 256>>>(x);                    // 1
    convw_all<<<dim3(16384, 7), 256>>>(Wr1, Wlv, Wg1, Wm, Wl, W1, W2); // 2
    // 3) h = relu(xf @ Wr1^T + br1) -> fp16   [PROFILED LAUNCH]
    gemm_f16<<<dim3(HH/128, MT), blk, SMEMF>>>(xf, Wr1fh, Wr1fl, br1,
        nullptr, hff, nullptr, nullptr, nullptr, BB, HH, DD, 1|2|8);
    // 4) var/w: f32 outputs for miss rows + w -> fp16 wvf
    gemm_f16<<<dim3(PP/128, MT), blk, SMEMF>>>(hff, Wlvfh, Wlvfl, blv,
        out_var, wvf, out_w, eps_w, nullptr, BB, PP, HH, 1|32);
    convpT_kernel<<<dim3(DD/32, PP/32), dim3(32, 8)>>>(priors);     // 5
    // 6) x_rec = w @ pT^T -> fp16
    gemm_f16<<<dim3(DD/128, MT), blk, SMEMF>>>(wvf, pTfh, pTfl, nullptr,
        nullptr, xrf, nullptr, nullptr, nullptr, BB, DD, PP, 1|8);
    // 7) hr = relu(x_rec @ Wg1^T + bg1) -> fp16
    gemm_f16<<<dim3(HH/128, MT), blk, SMEMF>>>(xrf, Wg1fh, Wg1fl, bg1,
        nullptr, hrf, nullptr, nullptr, nullptr, BB, HH, DD, 1|2|8);
    concatb_kernel<<<(2*DD)/256, 256>>>(bm, bl);                    // 8
    // 9) fused dual: interleaved [mean|lreg] -> x_reg scatter into cbf
    gemm_f16<<<dim3((2*DD)/128, MT), blk, SMEMF>>>(hrf, Wcfh, Wcfl, pbcat,
        nullptr, cbf, nullptr, eps_r, xrf, BB, 2*DD, HH, 1|16);
    copy_kernel<<<dim3(DD/1024, BB), 256>>>(x);                     // 10
    // 11) h1 = relu(comb @ W1^T + b1) -> fp16
    gemm_f16<<<dim3(HH/128, MT), blk, SMEMF>>>(cbf, W1fh, W1fl, b1,
        nullptr, h1f, nullptr, nullptr, nullptr, BB, HH, DD, 2|8);
    // 12) logits = h1 @ W2^T + b2 -> f32
    gemm_f16<<<dim3((OO+127)/128, MT), blk, SMEMF>>>(h1f, W2fh, W2fl, b2,
        out_logits, nullptr, nullptr, nullptr, nullptr, BB, OO, HH, 4);
}

// round 16
// speedup vs baseline: 1.0831x; 1.0831x over previous
#include <cuda_runtime.h>
#include <cuda_bf16.h>
#include <cuda_fp16.h>
#include <cstdint>

#define BB 4096
#define DD 4096
#define HH 4096
#define OO 1000
#define PP 2048

typedef __half hf;

// ---- device scratch ----
__device__ hf g_Wr1fh[(size_t)HH*DD], g_Wr1fl[(size_t)HH*DD];
__device__ hf g_Wlvfh[(size_t)PP*HH], g_Wlvfl[(size_t)PP*HH];
__device__ hf g_Wg1fh[(size_t)HH*DD], g_Wg1fl[(size_t)HH*DD];
__device__ hf g_Wcfh [(size_t)2*DD*HH], g_Wcfl [(size_t)2*DD*HH]; // Wm/Wl row-interleaved
__device__ hf g_W1fh[(size_t)HH*DD], g_W1fl[(size_t)HH*DD];
__device__ hf g_W2fh[(size_t)OO*HH], g_W2fl[(size_t)OO*HH];
__device__ hf g_pTfh[(size_t)DD*PP], g_pTfl[(size_t)DD*PP];
__device__ hf g_xf  [(size_t)BB*DD];
__device__ hf g_hf  [(size_t)BB*HH];
__device__ hf g_wvf [(size_t)BB*PP];
__device__ hf g_xrf [(size_t)BB*DD];
__device__ hf g_hrf [(size_t)BB*HH];
__device__ hf g_cbf [(size_t)BB*DD];
__device__ hf g_h1f [(size_t)BB*HH];
__device__ float g_bcat[2*DD];
__device__ int g_na, g_perm[BB], g_newpos[BB], g_act[BB], g_posinact[BB], g_mask[BB];

// ---- helpers ----
__device__ __forceinline__ float softplusf(float z) {
    return fmaxf(z, 0.0f) + log1pf(expf(-fabsf(z)));
}
__device__ __forceinline__ uint32_t smem_u32(const void* p) {
    uint32_t a;
    asm("{ .reg .u64 t; cvta.to.shared.u64 t, %1; cvt.u32.u64 %0, t; }" : "=r"(a) : "l"(p));
    return a;
}
__device__ __forceinline__ void cpa16(uint32_t dst, const void* src) {
    asm volatile("cp.async.cg.shared.global [%0], [%1], 16;" :: "r"(dst), "l"(src));
}
__device__ __forceinline__ void ldmx4(uint32_t* r, uint32_t a) {
    asm volatile("ldmatrix.sync.aligned.m8n8.x4.shared.b16 {%0,%1,%2,%3}, [%4];"
                 : "=r"(r[0]), "=r"(r[1]), "=r"(r[2]), "=r"(r[3]) : "r"(a));
}
__device__ __forceinline__ void mma16816h(float* c, const uint32_t* a, const uint32_t* b) {
    asm("mma.sync.aligned.m16n8k16.row.col.f32.f16.f16.f32 "
        "{%0,%1,%2,%3}, {%4,%5,%6,%7}, {%8,%9}, {%0,%1,%2,%3};"
        : "+f"(c[0]), "+f"(c[1]), "+f"(c[2]), "+f"(c[3])
        : "r"(a[0]), "r"(a[1]), "r"(a[2]), "r"(a[3]), "r"(b[0]), "r"(b[1]));
}
__device__ __forceinline__ void split_f16(float v, hf& h, hf& l) {
    h = __float2half_rn(v);
    l = __float2half_rn(v - __half2float(h));
}

// ---- setup ----
__global__ void setup_kernel(const int* __restrict__ mm) {
    __shared__ int wsum[32];
    __shared__ int sTot[2];
    int tid = threadIdx.x, lane = tid & 31, warp = tid >> 5;
    int base = tid * 4;
    int f[4], incl[4], s = 0;
#pragma unroll
    for (int j = 0; j < 4; ++j) { f[j] = (mm[base + j] % 2 != 0); s += f[j]; incl[j] = s; }
    int v = s;
#pragma unroll
    for (int o = 1; o < 32; o <<= 1) { int u = __shfl_up_sync(~0u, v, o); if (lane >= o) v += u; }
    if (lane == 31) wsum[warp] = v;
    __syncthreads();
    if (warp == 0) {
        int w = wsum[lane];
#pragma unroll
        for (int o = 1; o < 32; o <<= 1) { int u = __shfl_up_sync(~0u, w, o); if (lane >= o) w += u; }
        wsum[lane] = w;
        if (lane == 31) sTot[0] = w;
    }
    __syncthreads();
    int Z = BB - sTot[0];
    int thrExcl = (warp ? wsum[warp - 1] : 0) + (v - s);
    int af[4];
#pragma unroll
    for (int j = 0; j < 4; ++j) {
        int i = base + j;
        int ones = thrExcl + incl[j] - f[j];
        int pos = f[j] ? (Z + ones) : (i - ones);
        g_mask[i] = f[j]; g_newpos[i] = pos; g_perm[pos] = i;
        af[j] = (f[j] || pos >= BB / 2);
    }
    __syncthreads();
    int incl2[4], s2 = 0;
#pragma unroll
    for (int j = 0; j < 4; ++j) { s2 += af[j]; incl2[j] = s2; }
    int v2 = s2;
#pragma unroll
    for (int o = 1; o < 32; o <<= 1) { int u = __shfl_up_sync(~0u, v2, o); if (lane >= o) v2 += u; }
    if (lane == 31) wsum[warp] = v2;
    __syncthreads();
    if (warp == 0) {
        int w = wsum[lane];
#pragma unroll
        for (int o = 1; o < 32; o <<= 1) { int u = __shfl_up_sync(~0u, w, o); if (lane >= o) w += u; }
        wsum[lane] = w;
        if (lane == 31) sTot[1] = w;
    }
    __syncthreads();
    int thrExcl2 = (warp ? wsum[warp - 1] : 0) + (v2 - s2);
#pragma unroll
    for (int j = 0; j < 4; ++j) {
        int i = base + j;
        int ab = thrExcl2 + incl2[j] - af[j];
        if (af[j]) { g_act[ab] = i; g_posinact[i] = ab; } else g_posinact[i] = -1;
    }
    if (tid == 0) g_na = sTot[1];
}

// ---- batched weight conversion (all fp16 hi/lo) ----
__global__ void convw_all(const float* __restrict__ Wr1, const float* __restrict__ Wlv,
                          const float* __restrict__ Wg1, const float* __restrict__ Wm,
                          const float* __restrict__ Wl,  const float* __restrict__ W1,
                          const float* __restrict__ W2) {
    int seg = blockIdx.y;
    size_t i = ((size_t)blockIdx.x * 256 + threadIdx.x) * 4;
    const float* src;
    size_t n;
    switch (seg) {
        case 0: src = Wr1; n = (size_t)HH * DD; break;
        case 1: src = Wg1; n = (size_t)HH * DD; break;
        case 2: src = W1;  n = (size_t)HH * DD; break;
        case 3: src = Wlv; n = (size_t)PP * HH; break;
        case 4: src = W2;  n = (size_t)OO * HH; break;
        case 5: src = Wm;  n = (size_t)DD * HH; break;
        default: src = Wl; n = (size_t)DD * HH; break;
    }
    if (i >= n) return;
    float4 v = *reinterpret_cast<const float4*>(src + i);
    float vv[4] = {v.x, v.y, v.z, v.w};
    hf *hi, *lo;
    size_t o = i;
    switch (seg) {
        case 0: hi = g_Wr1fh; lo = g_Wr1fl; break;
        case 1: hi = g_Wg1fh; lo = g_Wg1fl; break;
        case 2: hi = g_W1fh;  lo = g_W1fl;  break;
        case 3: hi = g_Wlvfh; lo = g_Wlvfl; break;
        case 4: hi = g_W2fh;  lo = g_W2fl;  break;
        default: {
            hi = g_Wcfh; lo = g_Wcfl;
            size_t row = i / HH, col = i - row * HH;
            o = (row * 2 + (seg - 5)) * HH + col;
        }
    }
    hf h[4], l[4];
#pragma unroll
    for (int j = 0; j < 4; ++j) split_f16(vv[j], h[j], l[j]);
    reinterpret_cast<__half2*>(hi + o)[0] = __half2(h[0], h[1]);
    reinterpret_cast<__half2*>(hi + o)[1] = __half2(h[2], h[3]);
    reinterpret_cast<__half2*>(lo + o)[0] = __half2(l[0], l[1]);
    reinterpret_cast<__half2*>(lo + o)[1] = __half2(l[2], l[3]);
}

__global__ void convx_kernel(const float* __restrict__ x) {
    int i = blockIdx.y;
    if (i >= g_na) return;
    int r = g_act[i];
    int d = (blockIdx.x * 256 + threadIdx.x) * 4;
    float4 v = *reinterpret_cast<const float4*>(x + (size_t)r * DD + d);
    size_t o = (size_t)i * DD + d;
    reinterpret_cast<__half2*>(g_xf + o)[0] = __floats2half2_rn(v.x, v.y);
    reinterpret_cast<__half2*>(g_xf + o)[1] = __floats2half2_rn(v.z, v.w);
}
__global__ void convpT_kernel(const float* __restrict__ P) {
    __shared__ float tile[32][33];
    int d0 = blockIdx.x * 32, p0 = blockIdx.y * 32;
    int tx = threadIdx.x, ty = threadIdx.y;
#pragma unroll
    for (int i = 0; i < 4; ++i)
        tile[ty + i * 8][tx] = P[(size_t)(p0 + ty + i * 8) * DD + d0 + tx];
    __syncthreads();
#pragma unroll
    for (int i = 0; i < 4; ++i) {
        hf h, l;
        split_f16(tile[tx][ty + i * 8], h, l);
        size_t o = (size_t)(d0 + ty + i * 8) * PP + p0 + tx;
        g_pTfh[o] = h; g_pTfl[o] = l;
    }
}
__global__ void concatb_kernel(const float* __restrict__ a, const float* __restrict__ b) {
    int i = blockIdx.x * 256 + threadIdx.x;   // interleaved: even=bm, odd=bl
    g_bcat[i] = (i & 1) ? b[i >> 1] : a[i >> 1];
}

// ================= fp16 2-product GEMM, 256x128 CTA tile =================
// 512 threads, 16 warps, warp tile 64x32, 3-stage cp.async, 1 CTA/SM.
// A fragments single-buffered, B fragments double-buffered across kh.
// flags: 1=Meff g_na, 2=relu, 4=f32 out (Cf), 8=fp16 out (Chf), 16=dual-xreg, 32=var/w
#define ROWB 144
#define TILE_A (256 * ROWB)      // 36864
#define TILE_BB (128 * ROWB)     // 18432
#define STAGE_F (TILE_A + 2 * TILE_BB)   // 73728
#define NSTG 3
#define SMEMF (NSTG * STAGE_F + 512)

__global__ void __launch_bounds__(512, 1)
gemm_f16(const hf* __restrict__ A, const hf* __restrict__ Bh, const hf* __restrict__ Bl,
         const float* __restrict__ bias, float* __restrict__ Cf, hf* __restrict__ Chf,
         float* __restrict__ Cw, const float* __restrict__ eps, const hf* __restrict__ Xr,
         int M, int N, int K, int flags)
{
    int Meff = (flags & 1) ? g_na : M;
    int mT = blockIdx.y * 256;
    if (mT >= Meff) return;
    int nT = blockIdx.x * 128;

    extern __shared__ char sm[];
    uint32_t sb = smem_u32(sm);
    float* biasS = reinterpret_cast<float*>(sm + NSTG * STAGE_F);

    int tid = threadIdx.x, wid = tid >> 5, lane = tid & 31;
    int wm = wid & 3, wn = wid >> 2;   // warp tile: 64 rows (wm), 32 cols (wn)

    if (tid < 128) {
        int n = nT + tid;
        biasS[tid] = (bias && n < N) ? bias[n] : 0.0f;
    }

    uint32_t aBase = (wm * 64 + (lane & 15)) * ROWB + ((lane >> 4) & 1) * 16;
    uint32_t bBase = TILE_A + (wn * 32 + ((lane >> 4) & 1) * 8 + (lane & 7)) * ROWB +
                     ((lane >> 3) & 1) * 16;

    float acc[4][4][4];
#pragma unroll
    for (int a = 0; a < 4; ++a)
#pragma unroll
        for (int b = 0; b < 4; ++b)
#pragma unroll
            for (int c = 0; c < 4; ++c) acc[a][b][c] = 0.0f;

    int nK = K / 64;

#define LOAD_STAGE_F(s, k0)                                                      \
    {                                                                            \
        uint32_t st = sb + (s) * STAGE_F;                                        \
        _Pragma("unroll")                                                        \
        for (int i = 0; i < 4; ++i) {                                            \
            int idx = i * 512 + tid;                                             \
            int r = idx >> 3, c16 = idx & 7;                                     \
            int rg = mT + r; rg = rg < Meff ? rg : Meff - 1;                     \
            size_t go = (size_t)rg * K + (k0) + c16 * 8;                         \
            cpa16(st + r * ROWB + c16 * 16, A + go);                             \
        }                                                                        \
        _Pragma("unroll")                                                        \
        for (int i = 0; i < 2; ++i) {                                            \
            int idx = i * 512 + tid;                                             \
            int r = idx >> 3, c16 = idx & 7;                                     \
            int rg = nT + r; rg = rg < N ? rg : N - 1;                           \
            size_t go = (size_t)rg * K + (k0) + c16 * 8;                         \
            uint32_t off = r * ROWB + c16 * 16;                                  \
            cpa16(st + TILE_A + off, Bh + go);                                   \
            cpa16(st + TILE_A + TILE_BB + off, Bl + go);                         \
        }                                                                        \
    }

#define LOAD_A_F(st, kh, AR)                                                     \
    {                                                                            \
        uint32_t ab = (st) + aBase + (kh) * 32;                                  \
        _Pragma("unroll")                                                        \
        for (int ma = 0; ma < 4; ++ma) ldmx4(AR[ma], ab + ma * 16 * ROWB);       \
    }

#define LOAD_B_F(st, kh, BH, BL)                                                 \
    {                                                                            \
        uint32_t bb = (st) + bBase + (kh) * 32;                                  \
        _Pragma("unroll")                                                        \
        for (int p = 0; p < 2; ++p) {                                            \
            uint32_t t[4];                                                       \
            ldmx4(t, bb + p * 16 * ROWB);                                        \
            BH[2*p][0] = t[0]; BH[2*p][1] = t[1];                                \
            BH[2*p+1][0] = t[2]; BH[2*p+1][1] = t[3];                            \
            ldmx4(t, bb + p * 16 * ROWB + TILE_BB);                              \
            BL[2*p][0] = t[0]; BL[2*p][1] = t[1];                                \
            BL[2*p+1][0] = t[2]; BL[2*p+1][1] = t[3];                            \
        }                                                                        \
    }

// product-major: 16 independent MMAs between accumulator reuse
#define MMA_BLOCK_F(AR, BH, BL)                                                  \
    {                                                                            \
        _Pragma("unroll")                                                        \
        for (int ma = 0; ma < 4; ++ma)                                           \
            _Pragma("unroll")                                                    \
            for (int na = 0; na < 4; ++na) mma16816h(acc[ma][na], AR[ma], BH[na]);\
        _Pragma("unroll")                                                        \
        for (int ma = 0; ma < 4; ++ma)                                           \
            _Pragma("unroll")                                                    \
            for (int na = 0; na < 4; ++na) mma16816h(acc[ma][na], AR[ma], BL[na]);\
    }

    LOAD_STAGE_F(0, 0);
    asm volatile("cp.async.commit_group;");
    LOAD_STAGE_F(1, 64);
    asm volatile("cp.async.commit_group;");

    uint32_t ar[4][4];
    uint32_t b0h[4][2], b0l[4][2];   // B buffer 0
    uint32_t b1h[4][2], b1l[4][2];   // B buffer 1

    asm volatile("cp.async.wait_group 1;");
    __syncthreads();
    LOAD_B_F(sb, 0, b0h, b0l);

    int s_cur = 0;
#pragma unroll 1
    for (int it = 0; it < nK; ++it) {
        uint32_t st = sb + s_cur * STAGE_F;
        // kh0
        LOAD_A_F(st, 0, ar);
        LOAD_B_F(st, 1, b1h, b1l);
        MMA_BLOCK_F(ar, b0h, b0l);
        // kh1
        LOAD_A_F(st, 1, ar);
        LOAD_B_F(st, 2, b0h, b0l);
        MMA_BLOCK_F(ar, b1h, b1l);
        // kh2
        LOAD_A_F(st, 2, ar);
        LOAD_B_F(st, 3, b1h, b1l);
        MMA_BLOCK_F(ar, b0h, b0l);
        // kh3
        LOAD_A_F(st, 3, ar);
        int ps = it + 2;
        int s_tgt = s_cur + 2 >= NSTG ? s_cur + 2 - NSTG : s_cur + 2;
        if (ps < nK) LOAD_STAGE_F(s_tgt, ps * 64);
        asm volatile("cp.async.commit_group;");
        MMA_BLOCK_F(ar, b1h, b1l);
        asm volatile("cp.async.wait_group 1;");
        __syncthreads();
        if (it + 1 < nK) {
            int s_n = s_cur + 1 == NSTG ? 0 : s_cur + 1;
            LOAD_B_F(sb + s_n * STAGE_F, 0, b0h, b0l);
        }
        s_cur = s_cur + 1 == NSTG ? 0 : s_cur + 1;
    }

    // ---- epilogue ----
    bool relu = flags & 2, f32s = flags & 4, hfs = flags & 8;
    bool dual = flags & 16, varw = flags & 32;
#pragma unroll
    for (int ma = 0; ma < 4; ++ma) {
#pragma unroll
        for (int rs = 0; rs < 2; ++rs) {
            int m = mT + wm * 64 + ma * 16 + (lane >> 2) + rs * 8;
            if (m >= Meff) continue;
            size_t ro = (size_t)m * N;
            int r = (dual || varw) ? g_act[m] : 0;
#pragma unroll
            for (int na = 0; na < 4; ++na) {
                int nc = wn * 32 + na * 8 + (lane & 3) * 2;
                int n = nT + nc;
                if (n >= N) continue;
                float v0 = acc[ma][na][rs * 2 + 0] + biasS[nc];
                float v1 = acc[ma][na][rs * 2 + 1] + biasS[nc + 1];
                if (relu) { v0 = fmaxf(v0, 0.0f); v1 = fmaxf(v1, 0.0f); }
                if (varw) {
                    float var0 = expf(v0), var1 = expf(v1);
                    float w0 = 1.0f + sqrtf(var0) * eps[(size_t)r * N + n];
                    float w1 = 1.0f + sqrtf(var1) * eps[(size_t)r * N + n + 1];
                    int np = g_newpos[r];
                    if (np >= BB / 2) {
                        size_t jo = (size_t)(np - BB / 2) * N + n;
                        *reinterpret_cast<float2*>(Cf + jo) = make_float2(var0, var1);
                        *reinterpret_cast<float2*>(Cw + jo) = make_float2(w0, w1);
                    }
                    *reinterpret_cast<__half2*>(Chf + ro + n) = __floats2half2_rn(w0, w1);
                } else if (dual) {
                    if (g_mask[r]) {
                        int d = n >> 1;
                        float xr = __half2float(Xr[(size_t)m * DD + d]);
                        float ep = eps[(size_t)r * DD + d];
                        float o = xr * softplusf(v0 + expf(0.5f * v1) * ep);
                        size_t dst = (size_t)g_newpos[r] * DD + d;
                        Chf[dst] = __float2half_rn(o);
                    }
                } else {
                    if (f32s)
                        *reinterpret_cast<float2*>(Cf + ro + n) = make_float2(v0, v1);
                    if (hfs)
                        *reinterpret_cast<__half2*>(Chf + ro + n) = __floats2half2_rn(v0, v1);
                }
            }
        }
    }
}

// ---- elementwise ----
__global__ void copy_kernel(const float* __restrict__ x) {
    int j = blockIdx.y;
    int r = g_perm[j];
    if (g_mask[r]) return;
    int d = (blockIdx.x * 256 + threadIdx.x) * 4;
    float4 v = *reinterpret_cast<const float4*>(x + (size_t)r * DD + d);
    size_t dst = (size_t)j * DD + d;
    reinterpret_cast<__half2*>(g_cbf + dst)[0] = __floats2half2_rn(v.x, v.y);
    reinterpret_cast<__half2*>(g_cbf + dst)[1] = __floats2half2_rn(v.z, v.w);
}

// ---- launch ----
static void* sa(const void* s) { void* p = nullptr; cudaGetSymbolAddress(&p, s); return p; }

extern "C" void kernel_launch(void* const* d_in, const int* in_sizes, int n_in,
                              void* d_out, int out_size) {
    const float* x      = (const float*)d_in[0];
    const int*   mm     = (const int*)d_in[1];
    const float* priors = (const float*)d_in[2];
    const float* W1  = (const float*)d_in[3];
    const float* b1  = (const float*)d_in[4];
    const float* W2  = (const float*)d_in[5];
    const float* b2  = (const float*)d_in[6];
    const float* Wr1 = (const float*)d_in[7];
    const float* br1 = (const float*)d_in[8];
    const float* Wlv = (const float*)d_in[9];
    const float* blv = (const float*)d_in[10];
    const float* Wg1 = (const float*)d_in[11];
    const float* bg1 = (const float*)d_in[12];
    const float* Wm  = (const float*)d_in[13];
    const float* bm  = (const float*)d_in[14];
    const float* Wl  = (const float*)d_in[15];
    const float* bl  = (const float*)d_in[16];
    const float* eps_w = (const float*)d_in[17];
    const float* eps_r = (const float*)d_in[18];
    float* out = (float*)d_out;
    float* out_logits = out;
    float* out_w = out + (size_t)BB * OO;
    float* out_var = out_w + (size_t)(BB - BB / 2) * PP;

    cudaFuncSetAttribute(gemm_f16, cudaFuncAttributeMaxDynamicSharedMemorySize, SMEMF);

    hf *Wr1fh=(hf*)sa(g_Wr1fh), *Wr1fl=(hf*)sa(g_Wr1fl);
    hf *Wlvfh=(hf*)sa(g_Wlvfh), *Wlvfl=(hf*)sa(g_Wlvfl);
    hf *Wg1fh=(hf*)sa(g_Wg1fh), *Wg1fl=(hf*)sa(g_Wg1fl);
    hf *Wcfh=(hf*)sa(g_Wcfh), *Wcfl=(hf*)sa(g_Wcfl);
    hf *W1fh=(hf*)sa(g_W1fh), *W1fl=(hf*)sa(g_W1fl);
    hf *W2fh=(hf*)sa(g_W2fh), *W2fl=(hf*)sa(g_W2fl);
    hf *pTfh=(hf*)sa(g_pTfh), *pTfl=(hf*)sa(g_pTfl);
    hf *xf=(hf*)sa(g_xf), *hff=(hf*)sa(g_hf);
    hf *wvf=(hf*)sa(g_wvf), *xrf=(hf*)sa(g_xrf), *hrf=(hf*)sa(g_hrf);
    hf *cbf=(hf*)sa(g_cbf), *h1f=(hf*)sa(g_h1f);
    float *pbcat=(float*)sa(g_bcat);

    dim3 blk(512);
    const int MT = BB / 256;   // 16 m-tiles

    setup_kernel<<<1, 1024>>>(mm);                                  // 0
    convx_kernel<<<dim3(DD/1024, BB), 256>>>(x);                    // 1
    convw_all<<<dim3(16384, 7), 256>>>(Wr1, Wlv, Wg1, Wm, Wl, W1, W2); // 2
    // 3) h = relu(xf @ Wr1^T + br1) -> fp16   [PROFILED LAUNCH]
    gemm_f16<<<dim3(HH/128, MT), blk, SMEMF>>>(xf, Wr1fh, Wr1fl, br1,
        nullptr, hff, nullptr, nullptr, nullptr, BB, HH, DD, 1|2|8);
    // 4) var/w
    gemm_f16<<<dim3(PP/128, MT), blk, SMEMF>>>(hff, Wlvfh, Wlvfl, blv,
        out_var, wvf, out_w, eps_w, nullptr, BB, PP, HH, 1|32);
    convpT_kernel<<<dim3(DD/32, PP/32), dim3(32, 8)>>>(priors);     // 5
    // 6) x_rec = w @ pT^T -> fp16
    gemm_f16<<<dim3(DD/128, MT), blk, SMEMF>>>(wvf, pTfh, pTfl, nullptr,
        nullptr, xrf, nullptr, nullptr, nullptr, BB, DD, PP, 1|8);
    // 7) hr = relu(x_rec @ Wg1^T + bg1) -> fp16
    gemm_f16<<<dim3(HH/128, MT), blk, SMEMF>>>(xrf, Wg1fh, Wg1fl, bg1,
        nullptr, hrf, nullptr, nullptr, nullptr, BB, HH, DD, 1|2|8);
    concatb_kernel<<<(2*DD)/256, 256>>>(bm, bl);                    // 8
    // 9) fused dual: [mean|lreg] -> x_reg scatter into cbf
    gemm_f16<<<dim3((2*DD)/128, MT), blk, SMEMF>>>(hrf, Wcfh, Wcfl, pbcat,
        nullptr, cbf, nullptr, eps_r, xrf, BB, 2*DD, HH, 1|16);
    copy_kernel<<<dim3(DD/1024, BB), 256>>>(x);                     // 10
    // 11) h1 = relu(comb @ W1^T + b1) -> fp16
    gemm_f16<<<dim3(HH/128, MT), blk, SMEMF>>>(cbf, W1fh, W1fl, b1,
        nullptr, h1f, nullptr, nullptr, nullptr, BB, HH, DD, 2|8);
    // 12) logits = h1 @ W2^T + b2 -> f32
    gemm_f16<<<dim3((OO+127)/128, MT), blk, SMEMF>>>(h1f, W2fh, W2fl, b2,
        out_logits, nullptr, nullptr, nullptr, nullptr, BB, OO, HH, 4);
}

// round 17
// speedup vs baseline: 1.1276x; 1.0410x over previous
#include <cuda_runtime.h>
#include <cuda_bf16.h>
#include <cuda_fp16.h>
#include <cstdint>

#define BB 4096
#define DD 4096
#define HH 4096
#define OO 1000
#define PP 2048

typedef __half hf;

// ---- device scratch ----
__device__ hf g_Wr1fh[(size_t)HH*DD], g_Wr1fl[(size_t)HH*DD];
__device__ hf g_Wlvfh[(size_t)PP*HH], g_Wlvfl[(size_t)PP*HH];
__device__ hf g_Wg1fh[(size_t)HH*DD], g_Wg1fl[(size_t)HH*DD];
__device__ hf g_Wcfh [(size_t)2*DD*HH], g_Wcfl [(size_t)2*DD*HH]; // Wm/Wl row-interleaved
__device__ hf g_W1fh[(size_t)HH*DD], g_W1fl[(size_t)HH*DD];
__device__ hf g_W2fh[(size_t)OO*HH], g_W2fl[(size_t)OO*HH];
__device__ hf g_pTfh[(size_t)DD*PP], g_pTfl[(size_t)DD*PP];
__device__ hf g_xf  [(size_t)BB*DD];
__device__ hf g_hf  [(size_t)BB*HH];
__device__ hf g_wvf [(size_t)BB*PP];
__device__ hf g_xrf [(size_t)BB*DD];
__device__ hf g_hrf [(size_t)BB*HH];
__device__ hf g_cbf [(size_t)BB*DD];
__device__ hf g_h1f [(size_t)BB*HH];
__device__ float g_bcat[2*DD];
__device__ int g_na, g_perm[BB], g_newpos[BB], g_act[BB], g_posinact[BB], g_mask[BB];

// ---- helpers ----
__device__ __forceinline__ float softplusf(float z) {
    return fmaxf(z, 0.0f) + log1pf(expf(-fabsf(z)));
}
__device__ __forceinline__ uint32_t smem_u32(const void* p) {
    uint32_t a;
    asm("{ .reg .u64 t; cvta.to.shared.u64 t, %1; cvt.u32.u64 %0, t; }" : "=r"(a) : "l"(p));
    return a;
}
__device__ __forceinline__ void cpa16(uint32_t dst, const void* src) {
    asm volatile("cp.async.cg.shared.global [%0], [%1], 16;" :: "r"(dst), "l"(src));
}
__device__ __forceinline__ void ldmx4(uint32_t* r, uint32_t a) {
    asm volatile("ldmatrix.sync.aligned.m8n8.x4.shared.b16 {%0,%1,%2,%3}, [%4];"
                 : "=r"(r[0]), "=r"(r[1]), "=r"(r[2]), "=r"(r[3]) : "r"(a));
}
__device__ __forceinline__ void mma16816h(float* c, const uint32_t* a, const uint32_t* b) {
    asm("mma.sync.aligned.m16n8k16.row.col.f32.f16.f16.f32 "
        "{%0,%1,%2,%3}, {%4,%5,%6,%7}, {%8,%9}, {%0,%1,%2,%3};"
        : "+f"(c[0]), "+f"(c[1]), "+f"(c[2]), "+f"(c[3])
        : "r"(a[0]), "r"(a[1]), "r"(a[2]), "r"(a[3]), "r"(b[0]), "r"(b[1]));
}
__device__ __forceinline__ void split_f16(float v, hf& h, hf& l) {
    h = __float2half_rn(v);
    l = __float2half_rn(v - __half2float(h));
}

// ---- setup ----
__global__ void setup_kernel(const int* __restrict__ mm) {
    __shared__ int wsum[32];
    __shared__ int sTot[2];
    int tid = threadIdx.x, lane = tid & 31, warp = tid >> 5;
    int base = tid * 4;
    int f[4], incl[4], s = 0;
#pragma unroll
    for (int j = 0; j < 4; ++j) { f[j] = (mm[base + j] % 2 != 0); s += f[j]; incl[j] = s; }
    int v = s;
#pragma unroll
    for (int o = 1; o < 32; o <<= 1) { int u = __shfl_up_sync(~0u, v, o); if (lane >= o) v += u; }
    if (lane == 31) wsum[warp] = v;
    __syncthreads();
    if (warp == 0) {
        int w = wsum[lane];
#pragma unroll
        for (int o = 1; o < 32; o <<= 1) { int u = __shfl_up_sync(~0u, w, o); if (lane >= o) w += u; }
        wsum[lane] = w;
        if (lane == 31) sTot[0] = w;
    }
    __syncthreads();
    int Z = BB - sTot[0];
    int thrExcl = (warp ? wsum[warp - 1] : 0) + (v - s);
    int af[4];
#pragma unroll
    for (int j = 0; j < 4; ++j) {
        int i = base + j;
        int ones = thrExcl + incl[j] - f[j];
        int pos = f[j] ? (Z + ones) : (i - ones);
        g_mask[i] = f[j]; g_newpos[i] = pos; g_perm[pos] = i;
        af[j] = (f[j] || pos >= BB / 2);
    }
    __syncthreads();
    int incl2[4], s2 = 0;
#pragma unroll
    for (int j = 0; j < 4; ++j) { s2 += af[j]; incl2[j] = s2; }
    int v2 = s2;
#pragma unroll
    for (int o = 1; o < 32; o <<= 1) { int u = __shfl_up_sync(~0u, v2, o); if (lane >= o) v2 += u; }
    if (lane == 31) wsum[warp] = v2;
    __syncthreads();
    if (warp == 0) {
        int w = wsum[lane];
#pragma unroll
        for (int o = 1; o < 32; o <<= 1) { int u = __shfl_up_sync(~0u, w, o); if (lane >= o) w += u; }
        wsum[lane] = w;
        if (lane == 31) sTot[1] = w;
    }
    __syncthreads();
    int thrExcl2 = (warp ? wsum[warp - 1] : 0) + (v2 - s2);
#pragma unroll
    for (int j = 0; j < 4; ++j) {
        int i = base + j;
        int ab = thrExcl2 + incl2[j] - af[j];
        if (af[j]) { g_act[ab] = i; g_posinact[i] = ab; } else g_posinact[i] = -1;
    }
    if (tid == 0) g_na = sTot[1];
}

// ---- batched weight conversion (all fp16 hi/lo) ----
__global__ void convw_all(const float* __restrict__ Wr1, const float* __restrict__ Wlv,
                          const float* __restrict__ Wg1, const float* __restrict__ Wm,
                          const float* __restrict__ Wl,  const float* __restrict__ W1,
                          const float* __restrict__ W2) {
    int seg = blockIdx.y;
    size_t i = ((size_t)blockIdx.x * 256 + threadIdx.x) * 4;
    const float* src;
    size_t n;
    switch (seg) {
        case 0: src = Wr1; n = (size_t)HH * DD; break;
        case 1: src = Wg1; n = (size_t)HH * DD; break;
        case 2: src = W1;  n = (size_t)HH * DD; break;
        case 3: src = Wlv; n = (size_t)PP * HH; break;
        case 4: src = W2;  n = (size_t)OO * HH; break;
        case 5: src = Wm;  n = (size_t)DD * HH; break;
        default: src = Wl; n = (size_t)DD * HH; break;
    }
    if (i >= n) return;
    float4 v = *reinterpret_cast<const float4*>(src + i);
    float vv[4] = {v.x, v.y, v.z, v.w};
    hf *hi, *lo;
    size_t o = i;
    switch (seg) {
        case 0: hi = g_Wr1fh; lo = g_Wr1fl; break;
        case 1: hi = g_Wg1fh; lo = g_Wg1fl; break;
        case 2: hi = g_W1fh;  lo = g_W1fl;  break;
        case 3: hi = g_Wlvfh; lo = g_Wlvfl; break;
        case 4: hi = g_W2fh;  lo = g_W2fl;  break;
        default: {
            hi = g_Wcfh; lo = g_Wcfl;
            size_t row = i / HH, col = i - row * HH;
            o = (row * 2 + (seg - 5)) * HH + col;
        }
    }
    hf h[4], l[4];
#pragma unroll
    for (int j = 0; j < 4; ++j) split_f16(vv[j], h[j], l[j]);
    reinterpret_cast<__half2*>(hi + o)[0] = __half2(h[0], h[1]);
    reinterpret_cast<__half2*>(hi + o)[1] = __half2(h[2], h[3]);
    reinterpret_cast<__half2*>(lo + o)[0] = __half2(l[0], l[1]);
    reinterpret_cast<__half2*>(lo + o)[1] = __half2(l[2], l[3]);
}

__global__ void convx_kernel(const float* __restrict__ x) {
    int i = blockIdx.y;
    if (i >= g_na) return;
    int r = g_act[i];
    int d = (blockIdx.x * 256 + threadIdx.x) * 4;
    float4 v = *reinterpret_cast<const float4*>(x + (size_t)r * DD + d);
    size_t o = (size_t)i * DD + d;
    reinterpret_cast<__half2*>(g_xf + o)[0] = __floats2half2_rn(v.x, v.y);
    reinterpret_cast<__half2*>(g_xf + o)[1] = __floats2half2_rn(v.z, v.w);
}
__global__ void convpT_kernel(const float* __restrict__ P) {
    __shared__ float tile[32][33];
    int d0 = blockIdx.x * 32, p0 = blockIdx.y * 32;
    int tx = threadIdx.x, ty = threadIdx.y;
#pragma unroll
    for (int i = 0; i < 4; ++i)
        tile[ty + i * 8][tx] = P[(size_t)(p0 + ty + i * 8) * DD + d0 + tx];
    __syncthreads();
#pragma unroll
    for (int i = 0; i < 4; ++i) {
        hf h, l;
        split_f16(tile[tx][ty + i * 8], h, l);
        size_t o = (size_t)(d0 + ty + i * 8) * PP + p0 + tx;
        g_pTfh[o] = h; g_pTfl[o] = l;
    }
}
__global__ void concatb_kernel(const float* __restrict__ a, const float* __restrict__ b) {
    int i = blockIdx.x * 256 + threadIdx.x;   // interleaved: even=bm, odd=bl
    g_bcat[i] = (i & 1) ? b[i >> 1] : a[i >> 1];
}

// ================= fp16 2-product GEMM, 128x128 CTA, 256 thr, 2 CTA/SM ===========
// 8 warps, warp tile 64x32 (2 m-groups x 4 n-groups). 2-stage cp.async.
// A fragments single-buffered, B fragments double-buffered across kh.
// flags: 1=Meff g_na, 2=relu, 4=f32 out (Cf), 8=fp16 out (Chf), 16=dual-xreg, 32=var/w
#define ROWB 144
#define TILE_T (128 * ROWB)              // 18432 (A, Bh, Bl each)
#define STAGE_F (3 * TILE_T)             // 55296
#define NSTG 2
#define SMEMF (NSTG * STAGE_F + 512)     // 111104 * 2 CTAs = 222208 <= 228KB

__global__ void __launch_bounds__(256, 2)
gemm_f16(const hf* __restrict__ A, const hf* __restrict__ Bh, const hf* __restrict__ Bl,
         const float* __restrict__ bias, float* __restrict__ Cf, hf* __restrict__ Chf,
         float* __restrict__ Cw, const float* __restrict__ eps, const hf* __restrict__ Xr,
         int M, int N, int K, int flags)
{
    int Meff = (flags & 1) ? g_na : M;
    int mT = blockIdx.y * 128;
    if (mT >= Meff) return;
    int nT = blockIdx.x * 128;

    extern __shared__ char sm[];
    uint32_t sb = smem_u32(sm);
    float* biasS = reinterpret_cast<float*>(sm + NSTG * STAGE_F);

    int tid = threadIdx.x, wid = tid >> 5, lane = tid & 31;
    int wm = wid & 1, wn = wid >> 1;   // warp tile: 64 rows (wm), 32 cols (wn)

    if (tid < 128) {
        int n = nT + tid;
        biasS[tid] = (bias && n < N) ? bias[n] : 0.0f;
    }

    uint32_t aBase = (wm * 64 + (lane & 15)) * ROWB + ((lane >> 4) & 1) * 16;
    uint32_t bBase = TILE_T + (wn * 32 + ((lane >> 4) & 1) * 8 + (lane & 7)) * ROWB +
                     ((lane >> 3) & 1) * 16;

    float acc[4][4][4];
#pragma unroll
    for (int a = 0; a < 4; ++a)
#pragma unroll
        for (int b = 0; b < 4; ++b)
#pragma unroll
            for (int c = 0; c < 4; ++c) acc[a][b][c] = 0.0f;

    int nK = K / 64;

#define LOAD_STAGE_F(s, k0)                                                      \
    {                                                                            \
        uint32_t st = sb + (s) * STAGE_F;                                        \
        _Pragma("unroll")                                                        \
        for (int i = 0; i < 4; ++i) {                                            \
            int idx = i * 256 + tid;                                             \
            int r = idx >> 3, c16 = idx & 7;                                     \
            int rg = mT + r; rg = rg < Meff ? rg : Meff - 1;                     \
            size_t go = (size_t)rg * K + (k0) + c16 * 8;                         \
            cpa16(st + r * ROWB + c16 * 16, A + go);                             \
        }                                                                        \
        _Pragma("unroll")                                                        \
        for (int i = 0; i < 4; ++i) {                                            \
            int idx = i * 256 + tid;                                             \
            int r = idx >> 3, c16 = idx & 7;                                     \
            int rg = nT + r; rg = rg < N ? rg : N - 1;                           \
            size_t go = (size_t)rg * K + (k0) + c16 * 8;                         \
            uint32_t off = r * ROWB + c16 * 16;                                  \
            cpa16(st + TILE_T + off, Bh + go);                                   \
            cpa16(st + 2 * TILE_T + off, Bl + go);                               \
        }                                                                        \
    }

#define LOAD_A_F(st, kh, AR)                                                     \
    {                                                                            \
        uint32_t ab = (st) + aBase + (kh) * 32;                                  \
        _Pragma("unroll")                                                        \
        for (int ma = 0; ma < 4; ++ma) ldmx4(AR[ma], ab + ma * 16 * ROWB);       \
    }

#define LOAD_B_F(st, kh, BH, BL)                                                 \
    {                                                                            \
        uint32_t bb = (st) + bBase + (kh) * 32;                                  \
        _Pragma("unroll")                                                        \
        for (int p = 0; p < 2; ++p) {                                            \
            uint32_t t[4];                                                       \
            ldmx4(t, bb + p * 16 * ROWB);                                        \
            BH[2*p][0] = t[0]; BH[2*p][1] = t[1];                                \
            BH[2*p+1][0] = t[2]; BH[2*p+1][1] = t[3];                            \
            ldmx4(t, bb + p * 16 * ROWB + TILE_T);                               \
            BL[2*p][0] = t[0]; BL[2*p][1] = t[1];                                \
            BL[2*p+1][0] = t[2]; BL[2*p+1][1] = t[3];                            \
        }                                                                        \
    }

// product-major: 16 independent MMAs between accumulator reuse
#define MMA_BLOCK_F(AR, BH, BL)                                                  \
    {                                                                            \
        _Pragma("unroll")                                                        \
        for (int ma = 0; ma < 4; ++ma)                                           \
            _Pragma("unroll")                                                    \
            for (int na = 0; na < 4; ++na) mma16816h(acc[ma][na], AR[ma], BH[na]);\
        _Pragma("unroll")                                                        \
        for (int ma = 0; ma < 4; ++ma)                                           \
            _Pragma("unroll")                                                    \
            for (int na = 0; na < 4; ++na) mma16816h(acc[ma][na], AR[ma], BL[na]);\
    }

    LOAD_STAGE_F(0, 0);
    asm volatile("cp.async.commit_group;");

    uint32_t ar[4][4];
    uint32_t b0h[4][2], b0l[4][2];
    uint32_t b1h[4][2], b1l[4][2];

    asm volatile("cp.async.wait_group 0;");
    __syncthreads();
    LOAD_B_F(sb, 0, b0h, b0l);

#pragma unroll 1
    for (int it = 0; it < nK; ++it) {
        uint32_t st = sb + (it & 1) * STAGE_F;
        // issue next-stage load first: overlaps with this iter's MMAs
        if (it + 1 < nK) LOAD_STAGE_F((it + 1) & 1, (it + 1) * 64);
        asm volatile("cp.async.commit_group;");
        // kh0
        LOAD_A_F(st, 0, ar);
        LOAD_B_F(st, 1, b1h, b1l);
        MMA_BLOCK_F(ar, b0h, b0l);
        // kh1
        LOAD_A_F(st, 1, ar);
        LOAD_B_F(st, 2, b0h, b0l);
        MMA_BLOCK_F(ar, b1h, b1l);
        // kh2
        LOAD_A_F(st, 2, ar);
        LOAD_B_F(st, 3, b1h, b1l);
        MMA_BLOCK_F(ar, b0h, b0l);
        // kh3
        LOAD_A_F(st, 3, ar);
        MMA_BLOCK_F(ar, b1h, b1l);
        asm volatile("cp.async.wait_group 0;");
        __syncthreads();
        if (it + 1 < nK)
            LOAD_B_F(sb + ((it + 1) & 1) * STAGE_F, 0, b0h, b0l);
    }

    // ---- epilogue ----
    bool relu = flags & 2, f32s = flags & 4, hfs = flags & 8;
    bool dual = flags & 16, varw = flags & 32;
#pragma unroll
    for (int ma = 0; ma < 4; ++ma) {
#pragma unroll
        for (int rs = 0; rs < 2; ++rs) {
            int m = mT + wm * 64 + ma * 16 + (lane >> 2) + rs * 8;
            if (m >= Meff) continue;
            size_t ro = (size_t)m * N;
            int r = (dual || varw) ? g_act[m] : 0;
#pragma unroll
            for (int na = 0; na < 4; ++na) {
                int nc = wn * 32 + na * 8 + (lane & 3) * 2;
                int n = nT + nc;
                if (n >= N) continue;
                float v0 = acc[ma][na][rs * 2 + 0] + biasS[nc];
                float v1 = acc[ma][na][rs * 2 + 1] + biasS[nc + 1];
                if (relu) { v0 = fmaxf(v0, 0.0f); v1 = fmaxf(v1, 0.0f); }
                if (varw) {
                    float var0 = expf(v0), var1 = expf(v1);
                    float w0 = 1.0f + sqrtf(var0) * eps[(size_t)r * N + n];
                    float w1 = 1.0f + sqrtf(var1) * eps[(size_t)r * N + n + 1];
                    int np = g_newpos[r];
                    if (np >= BB / 2) {
                        size_t jo = (size_t)(np - BB / 2) * N + n;
                        *reinterpret_cast<float2*>(Cf + jo) = make_float2(var0, var1);
                        *reinterpret_cast<float2*>(Cw + jo) = make_float2(w0, w1);
                    }
                    *reinterpret_cast<__half2*>(Chf + ro + n) = __floats2half2_rn(w0, w1);
                } else if (dual) {
                    if (g_mask[r]) {
                        int d = n >> 1;
                        float xr = __half2float(Xr[(size_t)m * DD + d]);
                        float ep = eps[(size_t)r * DD + d];
                        float o = xr * softplusf(v0 + expf(0.5f * v1) * ep);
                        size_t dst = (size_t)g_newpos[r] * DD + d;
                        Chf[dst] = __float2half_rn(o);
                    }
                } else {
                    if (f32s)
                        *reinterpret_cast<float2*>(Cf + ro + n) = make_float2(v0, v1);
                    if (hfs)
                        *reinterpret_cast<__half2*>(Chf + ro + n) = __floats2half2_rn(v0, v1);
                }
            }
        }
    }
}

// ---- elementwise ----
__global__ void copy_kernel(const float* __restrict__ x) {
    int j = blockIdx.y;
    int r = g_perm[j];
    if (g_mask[r]) return;
    int d = (blockIdx.x * 256 + threadIdx.x) * 4;
    float4 v = *reinterpret_cast<const float4*>(x + (size_t)r * DD + d);
    size_t dst = (size_t)j * DD + d;
    reinterpret_cast<__half2*>(g_cbf + dst)[0] = __floats2half2_rn(v.x, v.y);
    reinterpret_cast<__half2*>(g_cbf + dst)[1] = __floats2half2_rn(v.z, v.w);
}

// ---- launch ----
static void* sa(const void* s) { void* p = nullptr; cudaGetSymbolAddress(&p, s); return p; }

extern "C" void kernel_launch(void* const* d_in, const int* in_sizes, int n_in,
                              void* d_out, int out_size) {
    const float* x      = (const float*)d_in[0];
    const int*   mm     = (const int*)d_in[1];
    const float* priors = (const float*)d_in[2];
    const float* W1  = (const float*)d_in[3];
    const float* b1  = (const float*)d_in[4];
    const float* W2  = (const float*)d_in[5];
    const float* b2  = (const float*)d_in[6];
    const float* Wr1 = (const float*)d_in[7];
    const float* br1 = (const float*)d_in[8];
    const float* Wlv = (const float*)d_in[9];
    const float* blv = (const float*)d_in[10];
    const float* Wg1 = (const float*)d_in[11];
    const float* bg1 = (const float*)d_in[12];
    const float* Wm  = (const float*)d_in[13];
    const float* bm  = (const float*)d_in[14];
    const float* Wl  = (const float*)d_in[15];
    const float* bl  = (const float*)d_in[16];
    const float* eps_w = (const float*)d_in[17];
    const float* eps_r = (const float*)d_in[18];
    float* out = (float*)d_out;
    float* out_logits = out;
    float* out_w = out + (size_t)BB * OO;
    float* out_var = out_w + (size_t)(BB - BB / 2) * PP;

    cudaFuncSetAttribute(gemm_f16, cudaFuncAttributeMaxDynamicSharedMemorySize, SMEMF);

    hf *Wr1fh=(hf*)sa(g_Wr1fh), *Wr1fl=(hf*)sa(g_Wr1fl);
    hf *Wlvfh=(hf*)sa(g_Wlvfh), *Wlvfl=(hf*)sa(g_Wlvfl);
    hf *Wg1fh=(hf*)sa(g_Wg1fh), *Wg1fl=(hf*)sa(g_Wg1fl);
    hf *Wcfh=(hf*)sa(g_Wcfh), *Wcfl=(hf*)sa(g_Wcfl);
    hf *W1fh=(hf*)sa(g_W1fh), *W1fl=(hf*)sa(g_W1fl);
    hf *W2fh=(hf*)sa(g_W2fh), *W2fl=(hf*)sa(g_W2fl);
    hf *pTfh=(hf*)sa(g_pTfh), *pTfl=(hf*)sa(g_pTfl);
    hf *xf=(hf*)sa(g_xf), *hff=(hf*)sa(g_hf);
    hf *wvf=(hf*)sa(g_wvf), *xrf=(hf*)sa(g_xrf), *hrf=(hf*)sa(g_hrf);
    hf *cbf=(hf*)sa(g_cbf), *h1f=(hf*)sa(g_h1f);
    float *pbcat=(float*)sa(g_bcat);

    dim3 blk(256);
    const int MT = BB / 128;   // 32 m-tiles

    setup_kernel<<<1, 1024>>>(mm);                                  // 0
    convx_kernel<<<dim3(DD/1024, BB), 256>>>(x);                    // 1
    convw_all<<<dim3(16384, 7), 256>>>(Wr1, Wlv, Wg1, Wm, Wl, W1, W2); // 2
    // 3) h = relu(xf @ Wr1^T + br1) -> fp16   [PROFILED LAUNCH]
    gemm_f16<<<dim3(HH/128, MT), blk, SMEMF>>>(xf, Wr1fh, Wr1fl, br1,
        nullptr, hff, nullptr, nullptr, nullptr, BB, HH, DD, 1|2|8);
    // 4) var/w
    gemm_f16<<<dim3(PP/128, MT), blk, SMEMF>>>(hff, Wlvfh, Wlvfl, blv,
        out_var, wvf, out_w, eps_w, nullptr, BB, PP, HH, 1|32);
    convpT_kernel<<<dim3(DD/32, PP/32), dim3(32, 8)>>>(priors);     // 5
    // 6) x_rec = w @ pT^T -> fp16
    gemm_f16<<<dim3(DD/128, MT), blk, SMEMF>>>(wvf, pTfh, pTfl, nullptr,
        nullptr, xrf, nullptr, nullptr, nullptr, BB, DD, PP, 1|8);
    // 7) hr = relu(x_rec @ Wg1^T + bg1) -> fp16
    gemm_f16<<<dim3(HH/128, MT), blk, SMEMF>>>(xrf, Wg1fh, Wg1fl, bg1,
        nullptr, hrf, nullptr, nullptr, nullptr, BB, HH, DD, 1|2|8);
    concatb_kernel<<<(2*DD)/256, 256>>>(bm, bl);                    // 8
    // 9) fused dual: [mean|lreg] -> x_reg scatter into cbf
    gemm_f16<<<dim3((2*DD)/128, MT), blk, SMEMF>>>(hrf, Wcfh, Wcfl, pbcat,
        nullptr, cbf, nullptr, eps_r, xrf, BB, 2*DD, HH, 1|16);
    copy_kernel<<<dim3(DD/1024, BB), 256>>>(x);                     // 10
    // 11) h1 = relu(comb @ W1^T + b1) -> fp16
    gemm_f16<<<dim3(HH/128, MT), blk, SMEMF>>>(cbf, W1fh, W1fl, b1,
        nullptr, h1f, nullptr, nullptr, nullptr, BB, HH, DD, 2|8);
    // 12) logits = h1 @ W2^T + b2 -> f32
    gemm_f16<<<dim3((OO+127)/128, MT), blk, SMEMF>>>(h1f, W2fh, W2fl, b2,
        out_logits, nullptr, nullptr, nullptr, nullptr, BB, OO, HH, 4);
}